// round 1
// baseline (speedup 1.0000x reference)
#include <cuda_runtime.h>
#include <cuda_bf16.h>
#include <math.h>

#define N_NODES 20000
#define N_EDGES 320000
#define N_GRAPHS 200
#define TOWERS 5
#define F 75
#define TF 375          // TOWERS * F
#define EDGE_DIM 50
#define N_ATTR 100
#define FOUT 15

// ---------------- static scratch ----------------
__device__ float g_x[N_NODES * F];          // current node features
__device__ float g_y[N_NODES * F];          // post-lin pre-BN
__device__ float g_xds[N_NODES * 750];      // [n][0:375]=xd(dst weights), [375:750]=xs(src weights)
__device__ float g_aggr[(size_t)N_NODES * 1500]; // [n][t][mean75|mn75|mx75|std75]
__device__ float g_S[N_NODES * 225];        // [n][t][45] = aggr@ [Wa|Wb|Wc]
__device__ float g_et[N_ATTR * TF];         // edge term incl b_pre
__device__ float g_Mfold[F * F];            // Wx @ W_lin
__device__ float g_bfold[F];
__device__ int   g_deg[N_NODES];
__device__ int   g_rowptr[N_NODES + 1];
__device__ int   g_cursor[N_NODES];
__device__ int   g_colsrc[N_EDGES];
__device__ int   g_colattr[N_EDGES];
__device__ float g_amp[N_NODES], g_att[N_NODES], g_invdeg[N_NODES];
__device__ float g_logsum;
__device__ float g_bnsum[F], g_bnsq[F];
__device__ float g_scale[F], g_shift[F];
__device__ float g_pooled[N_GRAPHS * F];

// ---------------- kernels ----------------
__global__ void k_gather_x(const int* __restrict__ x_idx, const float* __restrict__ emb) {
    int i = blockIdx.x * 256 + threadIdx.x;
    if (i < N_NODES * F) {
        int n = i / F, f = i - n * F;
        g_x[i] = emb[x_idx[n] * F + f];
    }
}

__global__ void k_init() {
    int i = blockIdx.x * 256 + threadIdx.x;
    if (i < N_NODES) g_deg[i] = 0;
    if (i < N_GRAPHS * F) g_pooled[i] = 0.f;
    if (i == 0) g_logsum = 0.f;
}

__global__ void k_count(const int* __restrict__ ei) {
    int i = blockIdx.x * 256 + threadIdx.x;
    if (i < N_EDGES) atomicAdd(&g_deg[ei[N_EDGES + i]], 1);
}

__global__ void k_scan() {
    __shared__ int part[1024];
    int t = threadIdx.x;
    const int CH = (N_NODES + 1023) / 1024;
    int s0 = t * CH, s1 = min(s0 + CH, N_NODES);
    int s = 0;
    for (int i = s0; i < s1; i++) s += g_deg[i];
    part[t] = s;
    __syncthreads();
    for (int off = 1; off < 1024; off <<= 1) {
        int v = 0;
        if (t >= off) v = part[t - off];
        __syncthreads();
        if (t >= off) part[t] += v;
        __syncthreads();
    }
    int run = (t == 0) ? 0 : part[t - 1];
    for (int i = s0; i < s1; i++) {
        g_rowptr[i] = run;
        g_cursor[i] = run;
        run += g_deg[i];
    }
    if (t == 1023) g_rowptr[N_NODES] = part[1023];
}

__global__ void k_logsum() {
    int i = blockIdx.x * 256 + threadIdx.x;
    float v = 0.f;
    if (i < N_NODES) v = logf((float)g_deg[i] + 1.0f);
    for (int o = 16; o; o >>= 1) v += __shfl_down_sync(0xffffffffu, v, o);
    if ((threadIdx.x & 31) == 0) atomicAdd(&g_logsum, v);
}

__global__ void k_scalers() {
    int i = blockIdx.x * 256 + threadIdx.x;
    if (i < N_NODES) {
        float avg = g_logsum / (float)N_NODES;
        float d = (float)g_deg[i];
        float dc = fmaxf(d, 1.f);
        float L = logf(dc + 1.f);
        g_amp[i] = L / avg;
        g_att[i] = avg / L;
        g_invdeg[i] = 1.f / dc;
    }
}

__global__ void k_scatter(const int* __restrict__ ei, const int* __restrict__ ea) {
    int i = blockIdx.x * 256 + threadIdx.x;
    if (i < N_EDGES) {
        int dst = ei[N_EDGES + i];
        int pos = atomicAdd(&g_cursor[dst], 1);
        g_colsrc[pos] = ei[i];
        g_colattr[pos] = ea[i];
    }
}

// per-layer: edge term table et[a][t*75+f]
__global__ void k_et(const float* __restrict__ edge_emb, const float* __restrict__ W_edge,
                     const float* __restrict__ b_edge, const float* __restrict__ W_pre,
                     const float* __restrict__ b_pre, int l) {
    __shared__ float e75[F];
    int a = blockIdx.x, t = threadIdx.x;
    if (t < F) {
        float acc = b_edge[l * F + t];
        for (int d = 0; d < EDGE_DIM; d++)
            acc += edge_emb[a * EDGE_DIM + d] * W_edge[(l * EDGE_DIM + d) * F + t];
        e75[t] = acc;
    }
    __syncthreads();
    if (t < TF) {
        int tw = t / F, f = t - tw * F;
        float acc = b_pre[(l * TOWERS + tw) * F + f];
        const float* Wp = W_pre + ((size_t)((l * TOWERS + tw) * 225 + 150)) * F + f;
        for (int c = 0; c < F; c++) acc += e75[c] * Wp[c * F];
        g_et[a * TF + t] = acc;
    }
}

// xd|xs GEMM: [N,75] @ [75,750] -> g_xds
__global__ void k_xds(const float* __restrict__ W_pre, int l) {
    __shared__ __align__(16) float As[64][76];
    __shared__ __align__(16) float Bs[75][64];
    int n0 = blockIdx.y * 64, j0 = blockIdx.x * 64;
    int tid = threadIdx.y * 16 + threadIdx.x;
    for (int idx = tid; idx < 64 * 75; idx += 256) {
        int r = idx / 75, k = idx - r * 75;
        int n = n0 + r;
        As[r][k] = (n < N_NODES) ? g_x[n * F + k] : 0.f;
    }
    for (int idx = tid; idx < 75 * 64; idx += 256) {
        int k = idx / 64, j = idx - k * 64;
        int jj = j0 + j;
        float v = 0.f;
        if (jj < 750) {
            int part = jj / TF;
            int r3 = jj - part * TF;
            int tw = r3 / F, f = r3 - tw * F;
            v = W_pre[((size_t)((l * TOWERS + tw) * 225 + part * F + k)) * F + f];
        }
        Bs[k][j] = v;
    }
    __syncthreads();
    float acc[4][4] = {};
    int ty = threadIdx.y, tx = threadIdx.x;
#pragma unroll 5
    for (int k = 0; k < 75; k++) {
        float a0 = As[ty * 4 + 0][k], a1 = As[ty * 4 + 1][k];
        float a2 = As[ty * 4 + 2][k], a3 = As[ty * 4 + 3][k];
        float4 b4 = *(const float4*)&Bs[k][tx * 4];
        acc[0][0] += a0 * b4.x; acc[0][1] += a0 * b4.y; acc[0][2] += a0 * b4.z; acc[0][3] += a0 * b4.w;
        acc[1][0] += a1 * b4.x; acc[1][1] += a1 * b4.y; acc[1][2] += a1 * b4.z; acc[1][3] += a1 * b4.w;
        acc[2][0] += a2 * b4.x; acc[2][1] += a2 * b4.y; acc[2][2] += a2 * b4.z; acc[2][3] += a2 * b4.w;
        acc[3][0] += a3 * b4.x; acc[3][1] += a3 * b4.y; acc[3][2] += a3 * b4.z; acc[3][3] += a3 * b4.w;
    }
#pragma unroll
    for (int i = 0; i < 4; i++) {
        int n = n0 + ty * 4 + i;
        if (n >= N_NODES) continue;
#pragma unroll
        for (int j = 0; j < 4; j++) {
            int jj = j0 + tx * 4 + j;
            if (jj < 750) g_xds[(size_t)n * 750 + jj] = acc[i][j];
        }
    }
}

// aggregation: one warp per dst node
__global__ void k_aggr() {
    int warp = (blockIdx.x * blockDim.x + threadIdx.x) >> 5;
    int lane = threadIdx.x & 31;
    if (warp >= N_NODES) return;
    int n = warp;
    float xd[12], sum[12], sq[12], mn[12], mx[12];
#pragma unroll
    for (int k = 0; k < 12; k++) {
        int f = lane + 32 * k;
        xd[k] = (f < TF) ? g_xds[(size_t)n * 750 + f] : 0.f;
        sum[k] = 0.f; sq[k] = 0.f; mn[k] = INFINITY; mx[k] = -INFINITY;
    }
    int e0 = g_rowptr[n], e1 = g_rowptr[n + 1];
    for (int e = e0; e < e1; e++) {
        int s = g_colsrc[e], a = g_colattr[e];
        const float* xsrow = g_xds + (size_t)s * 750 + TF;
        const float* etrow = g_et + a * TF;
#pragma unroll
        for (int k = 0; k < 12; k++) {
            int f = lane + 32 * k;
            if (f < TF) {
                float v = xd[k] + xsrow[f] + etrow[f];
                sum[k] += v; sq[k] += v * v;
                mn[k] = fminf(mn[k], v); mx[k] = fmaxf(mx[k], v);
            }
        }
    }
    float inv = g_invdeg[n];
    bool has = e1 > e0;
#pragma unroll
    for (int k = 0; k < 12; k++) {
        int f = lane + 32 * k;
        if (f < TF) {
            float mean = sum[k] * inv;
            float var = sq[k] * inv - mean * mean;
            float sd = sqrtf(fmaxf(var, 0.f) + 1e-5f);
            float mnv = has ? mn[k] : 0.f;
            float mxv = has ? mx[k] : 0.f;
            int tw = f / F, j = f - tw * F;
            float* out = g_aggr + (size_t)n * 1500 + tw * 300 + j;
            out[0] = mean; out[75] = mnv; out[150] = mxv; out[225] = sd;
        }
    }
}

// S GEMM: per tower, [N,300] @ [300,45]. block: 128 nodes x 45 outs, 240 threads, thread 8x3
__global__ void k_gemmS(const float* __restrict__ W_post, int l) {
    __shared__ float As[128][52];
    __shared__ float Bs[50][48];
    int t = blockIdx.y;
    int n0 = blockIdx.x * 128;
    int tid = threadIdx.x;
    int ty = tid / 15, tx = tid - ty * 15; // ty 0..15, tx 0..14
    float acc[8][3] = {};
    for (int kc = 0; kc < 300; kc += 50) {
        for (int idx = tid; idx < 128 * 50; idx += 240) {
            int r = idx / 50, kk = idx - r * 50;
            int n = n0 + r;
            As[r][kk] = (n < N_NODES) ? g_aggr[(size_t)n * 1500 + t * 300 + kc + kk] : 0.f;
        }
        for (int idx = tid; idx < 50 * 45; idx += 240) {
            int kk = idx / 45, jo = idx - kk * 45;
            int g = jo / FOUT, f = jo - g * FOUT;
            Bs[kk][jo] = W_post[((size_t)((l * TOWERS + t) * 975 + 75 + g * 300 + kc + kk)) * FOUT + f];
        }
        __syncthreads();
#pragma unroll 5
        for (int kk = 0; kk < 50; kk++) {
            float a[8], b[3];
#pragma unroll
            for (int i = 0; i < 8; i++) a[i] = As[ty * 8 + i][kk];
#pragma unroll
            for (int j = 0; j < 3; j++) b[j] = Bs[kk][tx * 3 + j];
#pragma unroll
            for (int i = 0; i < 8; i++)
#pragma unroll
                for (int j = 0; j < 3; j++) acc[i][j] += a[i] * b[j];
        }
        __syncthreads();
    }
#pragma unroll
    for (int i = 0; i < 8; i++) {
        int n = n0 + ty * 8 + i;
        if (n >= N_NODES) continue;
#pragma unroll
        for (int j = 0; j < 3; j++)
            g_S[n * 225 + t * 45 + tx * 3 + j] = acc[i][j];
    }
}

// per-layer fold: Mfold = Wx @ W_lin, bfold = b_post@W_lin + b_lin; zero bn accum
__global__ void k_fold(const float* __restrict__ W_post, const float* __restrict__ b_post,
                       const float* __restrict__ W_lin, const float* __restrict__ b_lin, int l) {
    int i = blockIdx.x * 256 + threadIdx.x;
    if (i < F * F) {
        int c = i / F, o = i - c * F;
        float acc = 0.f;
        for (int tf = 0; tf < F; tf++) {
            int t = tf / FOUT, f = tf - t * FOUT;
            acc += W_post[((size_t)((l * TOWERS + t) * 975 + c)) * FOUT + f] *
                   W_lin[(l * F + tf) * F + o];
        }
        g_Mfold[i] = acc;
    }
    if (i < F) {
        float bf = b_lin[l * F + i];
        for (int tf = 0; tf < F; tf++) {
            int t = tf / FOUT, f = tf - t * FOUT;
            bf += b_post[(l * TOWERS + t) * FOUT + f] * W_lin[(l * F + tf) * F + i];
        }
        g_bfold[i] = bf;
        g_bnsum[i] = 0.f;
        g_bnsq[i] = 0.f;
    }
}

// post+lin GEMM: y[n][o<75] = sum_{k<300} A[n][k]*B[k][o] + bfold
// A: [x(75) | S0(75) | amp*S1(75) | att*S2(75)], B: [Mfold; W_lin; W_lin; W_lin]
__global__ void k_gemm2(const float* __restrict__ W_lin, int l) {
    __shared__ float As[64][52];
    __shared__ float Bs[50][76];
    int n0 = blockIdx.x * 64;
    int tid = threadIdx.x;
    int ty = tid / 15, tx = tid - ty * 15; // ty 0..15, tx 0..14
    float acc[4][5] = {};
    for (int kc = 0; kc < 300; kc += 50) {
        for (int idx = tid; idx < 64 * 50; idx += 240) {
            int r = idx / 50, kk = idx - r * 50;
            int n = n0 + r;
            int k = kc + kk;
            float av = 0.f;
            if (n < N_NODES) {
                if (k < 75) av = g_x[n * F + k];
                else {
                    int q = k - 75;
                    int seg = q / 75, p = q - seg * 75;
                    int t = p / FOUT, f = p - t * FOUT;
                    float s = g_S[n * 225 + t * 45 + seg * FOUT + f];
                    av = (seg == 0) ? s : (seg == 1 ? s * g_amp[n] : s * g_att[n]);
                }
            }
            As[r][kk] = av;
        }
        for (int idx = tid; idx < 50 * 75; idx += 240) {
            int kk = idx / 75, o = idx - kk * 75;
            int k = kc + kk;
            float bv;
            if (k < 75) bv = g_Mfold[k * F + o];
            else {
                int q = (k - 75) % 75;
                bv = W_lin[(l * F + q) * F + o];
            }
            Bs[kk][o] = bv;
        }
        __syncthreads();
#pragma unroll 5
        for (int kk = 0; kk < 50; kk++) {
            float a[4], b[5];
#pragma unroll
            for (int i = 0; i < 4; i++) a[i] = As[ty * 4 + i][kk];
#pragma unroll
            for (int j = 0; j < 5; j++) b[j] = Bs[kk][tx * 5 + j];
#pragma unroll
            for (int i = 0; i < 4; i++)
#pragma unroll
                for (int j = 0; j < 5; j++) acc[i][j] += a[i] * b[j];
        }
        __syncthreads();
    }
#pragma unroll
    for (int i = 0; i < 4; i++) {
        int n = n0 + ty * 4 + i;
        if (n >= N_NODES) continue;
#pragma unroll
        for (int j = 0; j < 5; j++) {
            int o = tx * 5 + j;
            g_y[n * F + o] = acc[i][j] + g_bfold[o];
        }
    }
}

__global__ void k_bnreduce() {
    int o = threadIdx.x;
    if (o >= F) return;
    int n0 = blockIdx.x * 256, n1 = min(n0 + 256, N_NODES);
    float s = 0.f, q = 0.f;
    for (int n = n0; n < n1; n++) {
        float v = g_y[n * F + o];
        s += v; q += v * v;
    }
    atomicAdd(&g_bnsum[o], s);
    atomicAdd(&g_bnsq[o], q);
}

__global__ void k_bnfin(const float* __restrict__ gamma, const float* __restrict__ beta, int l) {
    int o = threadIdx.x;
    if (o < F) {
        float mu = g_bnsum[o] / (float)N_NODES;
        float var = g_bnsq[o] / (float)N_NODES - mu * mu;
        float r = rsqrtf(var + 1e-5f);
        float sc = r * gamma[l * F + o];
        g_scale[o] = sc;
        g_shift[o] = beta[l * F + o] - mu * sc;
    }
}

__global__ void k_apply() {
    int i = blockIdx.x * 256 + threadIdx.x;
    if (i < N_NODES * F) {
        int o = i % F;
        g_x[i] = fmaxf(g_y[i] * g_scale[o] + g_shift[o], 0.f);
    }
}

__global__ void k_pool(const int* __restrict__ batch) {
    int i = blockIdx.x * 256 + threadIdx.x;
    if (i < N_NODES * F) {
        int n = i / F, o = i - n * F;
        atomicAdd(&g_pooled[batch[n] * F + o], g_x[i]);
    }
}

__global__ void k_mlp(const float* __restrict__ W1, const float* __restrict__ b1,
                      const float* __restrict__ W2, const float* __restrict__ b2,
                      const float* __restrict__ W3, const float* __restrict__ b3,
                      float* __restrict__ out) {
    int g = threadIdx.x;
    if (g >= N_GRAPHS) return;
    const float* p = g_pooled + g * F;
    float h1[50];
    for (int j = 0; j < 50; j++) {
        float a = b1[j];
        for (int c = 0; c < F; c++) a += p[c] * W1[c * 50 + j];
        h1[j] = fmaxf(a, 0.f);
    }
    float h2[25];
    for (int j = 0; j < 25; j++) {
        float a = b2[j];
        for (int c = 0; c < 50; c++) a += h1[c] * W2[c * 25 + j];
        h2[j] = fmaxf(a, 0.f);
    }
    float o = b3[0];
    for (int c = 0; c < 25; c++) o += h2[c] * W3[c];
    out[g] = o;
}

// ---------------- launch ----------------
extern "C" void kernel_launch(void* const* d_in, const int* in_sizes, int n_in,
                              void* d_out, int out_size) {
    const int* x_idx = (const int*)d_in[0];
    const int* edge_index = (const int*)d_in[1];
    const int* eattr = (const int*)d_in[2];
    const int* batch = (const int*)d_in[3];
    const float* node_emb = (const float*)d_in[4];
    const float* edge_emb = (const float*)d_in[5];
    const float* W_edge = (const float*)d_in[6];
    const float* b_edge = (const float*)d_in[7];
    const float* W_pre = (const float*)d_in[8];
    const float* b_pre = (const float*)d_in[9];
    const float* W_post = (const float*)d_in[10];
    const float* b_post = (const float*)d_in[11];
    const float* W_lin = (const float*)d_in[12];
    const float* b_lin = (const float*)d_in[13];
    const float* gamma = (const float*)d_in[14];
    const float* beta = (const float*)d_in[15];
    const float* W1 = (const float*)d_in[16];
    const float* b1 = (const float*)d_in[17];
    const float* W2 = (const float*)d_in[18];
    const float* b2 = (const float*)d_in[19];
    const float* W3 = (const float*)d_in[20];
    const float* b3 = (const float*)d_in[21];
    float* out = (float*)d_out;

    const int NF = N_NODES * F;
    k_gather_x<<<(NF + 255) / 256, 256>>>(x_idx, node_emb);
    k_init<<<(N_NODES + 255) / 256, 256>>>();
    k_count<<<(N_EDGES + 255) / 256, 256>>>(edge_index);
    k_scan<<<1, 1024>>>();
    k_logsum<<<(N_NODES + 255) / 256, 256>>>();
    k_scalers<<<(N_NODES + 255) / 256, 256>>>();
    k_scatter<<<(N_EDGES + 255) / 256, 256>>>(edge_index, eattr);

    for (int l = 0; l < 2; l++) {
        k_et<<<N_ATTR, 384>>>(edge_emb, W_edge, b_edge, W_pre, b_pre, l);
        {
            dim3 grid(12, (N_NODES + 63) / 64);
            dim3 blk(16, 16);
            k_xds<<<grid, blk>>>(W_pre, l);
        }
        k_aggr<<<(N_NODES + 7) / 8, 256>>>();
        {
            dim3 grid((N_NODES + 127) / 128, TOWERS);
            k_gemmS<<<grid, 240>>>(W_post, l);
        }
        k_fold<<<(F * F + 255) / 256, 256>>>(W_post, b_post, W_lin, b_lin, l);
        k_gemm2<<<(N_NODES + 63) / 64, 240>>>(W_lin, l);
        k_bnreduce<<<(N_NODES + 255) / 256, 96>>>();
        k_bnfin<<<1, 96>>>(gamma, beta, l);
        k_apply<<<(NF + 255) / 256, 256>>>();
    }

    k_pool<<<(NF + 255) / 256, 256>>>(batch);
    k_mlp<<<1, 256>>>(W1, b1, W2, b2, W3, b3, out);
}

// round 2
// speedup vs baseline: 1.0838x; 1.0838x over previous
#include <cuda_runtime.h>
#include <cuda_bf16.h>
#include <math.h>

#define N_NODES 20000
#define N_EDGES 320000
#define N_GRAPHS 200
#define TOWERS 5
#define F 75
#define TF 375
#define EDGE_DIM 50
#define N_ATTR 100
#define FOUT 15
#define XSTRIDE 768   // padded row: xd[0..375) pad[375..384) xs[384..759) pad

// ---------------- static scratch (zero-initialized; pads never written) ----
__device__ float g_x[N_NODES * F];
__device__ float g_y[N_NODES * F];
__device__ float g_xds[(size_t)N_NODES * XSTRIDE];
__device__ float g_aggr[(size_t)N_NODES * 1500];   // [n][t][mean|mn|mx|std]
__device__ float g_S[N_NODES * F];                 // combined S per node (75)
__device__ float g_et[N_ATTR * 384];               // padded rows
__device__ float g_Mfold[F * F];
__device__ float g_bfold[F];
__device__ int   g_deg[N_NODES];
__device__ int   g_rowptr[N_NODES + 1];
__device__ int   g_cursor[N_NODES];
__device__ int   g_colsrc[N_EDGES];
__device__ int   g_colattr[N_EDGES];
__device__ float g_amp[N_NODES], g_att[N_NODES], g_invdeg[N_NODES];
__device__ float g_logsum;
__device__ int   g_part[128];
__device__ int   g_partscan[128];
__device__ float g_bnsum[F], g_bnsq[F];
__device__ float g_pooled[N_GRAPHS * F];

// ---------------- f32x2 helpers ----------------
__device__ __forceinline__ unsigned long long f2pk(float lo, float hi) {
    unsigned long long r;
    asm("mov.b64 %0, {%1, %2};" : "=l"(r) : "f"(lo), "f"(hi));
    return r;
}
__device__ __forceinline__ void f2up(unsigned long long v, float& lo, float& hi) {
    asm("mov.b64 {%0, %1}, %2;" : "=f"(lo), "=f"(hi) : "l"(v));
}
__device__ __forceinline__ unsigned long long ffma2(unsigned long long a, unsigned long long b, unsigned long long c) {
    unsigned long long d;
    asm("fma.rn.f32x2 %0, %1, %2, %3;" : "=l"(d) : "l"(a), "l"(b), "l"(c));
    return d;
}
__device__ __forceinline__ unsigned long long fadd2(unsigned long long a, unsigned long long b) {
    unsigned long long d;
    asm("add.rn.f32x2 %0, %1, %2;" : "=l"(d) : "l"(a), "l"(b));
    return d;
}

// ---------------- preprocessing ----------------
#define GATHER_BLKS ((N_NODES * F + 255) / 256)
#define COUNT_BLKS ((N_EDGES + 255) / 256)

__global__ void k_init() {
    int i = blockIdx.x * 256 + threadIdx.x;
    if (i < N_NODES) g_deg[i] = 0;
    if (i < N_GRAPHS * F) g_pooled[i] = 0.f;
    if (i == 0) g_logsum = 0.f;
}

__global__ void k_gather_count(const int* __restrict__ x_idx, const float* __restrict__ emb,
                               const int* __restrict__ ei) {
    int b = blockIdx.x;
    if (b < GATHER_BLKS) {
        int i = b * 256 + threadIdx.x;
        if (i < N_NODES * F) {
            int n = i / F, f = i - n * F;
            g_x[i] = emb[x_idx[n] * F + f];
        }
    } else {
        int i = (b - GATHER_BLKS) * 256 + threadIdx.x;
        if (i < N_EDGES) atomicAdd(&g_deg[ei[N_EDGES + i]], 1);
    }
}

#define SCAN_BLKS ((N_NODES + 255) / 256)

__global__ void k_scanA() {
    __shared__ int ss[256];
    __shared__ float ls[256];
    int b = blockIdx.x, tid = threadIdx.x;
    int n = b * 256 + tid;
    int d = (n < N_NODES) ? g_deg[n] : 0;
    ss[tid] = d;
    ls[tid] = (n < N_NODES) ? logf((float)d + 1.f) : 0.f;
    __syncthreads();
    for (int o = 128; o; o >>= 1) {
        if (tid < o) { ss[tid] += ss[tid + o]; ls[tid] += ls[tid + o]; }
        __syncthreads();
    }
    if (tid == 0) { g_part[b] = ss[0]; atomicAdd(&g_logsum, ls[0]); }
}

__global__ void k_scanB() {
    __shared__ int s[128];
    int t = threadIdx.x;
    int own = (t < SCAN_BLKS) ? g_part[t] : 0;
    s[t] = own;
    __syncthreads();
    for (int o = 1; o < 128; o <<= 1) {
        int v = (t >= o) ? s[t - o] : 0;
        __syncthreads();
        s[t] += v;
        __syncthreads();
    }
    if (t < SCAN_BLKS) g_partscan[t] = s[t] - own;  // exclusive
}

__global__ void k_scanC() {
    __shared__ int s[256];
    int b = blockIdx.x, tid = threadIdx.x;
    int n = b * 256 + tid;
    int d = (n < N_NODES) ? g_deg[n] : 0;
    int own = d;
    s[tid] = d;
    __syncthreads();
    for (int o = 1; o < 256; o <<= 1) {
        int v = (tid >= o) ? s[tid - o] : 0;
        __syncthreads();
        s[tid] += v;
        __syncthreads();
    }
    int excl = s[tid] - own + g_partscan[b];
    if (n < N_NODES) {
        g_rowptr[n] = excl;
        g_cursor[n] = excl;
        float avg = g_logsum * (1.f / (float)N_NODES);
        float dc = fmaxf((float)d, 1.f);
        float L = logf(dc + 1.f);
        g_amp[n] = L / avg;
        g_att[n] = avg / L;
        g_invdeg[n] = 1.f / dc;
        if (n == N_NODES - 1) g_rowptr[N_NODES] = excl + d;
    }
}

__global__ void k_scatter(const int* __restrict__ ei, const int* __restrict__ ea) {
    int i = blockIdx.x * 256 + threadIdx.x;
    if (i < N_EDGES) {
        int dst = ei[N_EDGES + i];
        int pos = atomicAdd(&g_cursor[dst], 1);
        g_colsrc[pos] = ei[i];
        g_colattr[pos] = ea[i];
    }
}

// ---------------- per-layer: et table + Mfold + bn zero ----------------
__global__ void k_et_fold(const float* __restrict__ edge_emb, const float* __restrict__ W_edge,
                          const float* __restrict__ b_edge, const float* __restrict__ W_pre,
                          const float* __restrict__ b_pre, const float* __restrict__ W_post,
                          const float* __restrict__ b_post, const float* __restrict__ W_lin,
                          const float* __restrict__ b_lin, int l) {
    int a = blockIdx.x, t = threadIdx.x;
    if (a < N_ATTR) {
        __shared__ float e75[F];
        if (t < F) {
            float acc = b_edge[l * F + t];
            for (int d = 0; d < EDGE_DIM; d++)
                acc += edge_emb[a * EDGE_DIM + d] * W_edge[(l * EDGE_DIM + d) * F + t];
            e75[t] = acc;
        }
        __syncthreads();
        if (t < TF) {
            int tw = t / F, f = t - tw * F;
            float acc = b_pre[(l * TOWERS + tw) * F + f];
            const float* Wp = W_pre + ((size_t)((l * TOWERS + tw) * 225 + 150)) * F + f;
            for (int c = 0; c < F; c++) acc += e75[c] * Wp[c * F];
            g_et[a * 384 + t] = acc;
        }
    } else {
        for (int i = t; i < F * F; i += 384) {
            int c = i / F, o = i - c * F;
            float acc = 0.f;
            for (int tf = 0; tf < F; tf++) {
                int tw = tf / FOUT, f = tf - tw * FOUT;
                acc += W_post[((size_t)((l * TOWERS + tw) * 975 + c)) * FOUT + f] *
                       W_lin[(l * F + tf) * F + o];
            }
            g_Mfold[i] = acc;
        }
        if (t < F) {
            float bf = b_lin[l * F + t];
            for (int tf = 0; tf < F; tf++) {
                int tw = tf / FOUT, f = tf - tw * FOUT;
                bf += b_post[(l * TOWERS + tw) * FOUT + f] * W_lin[(l * F + tf) * F + t];
            }
            g_bfold[t] = bf;
            g_bnsum[t] = 0.f;
            g_bnsq[t] = 0.f;
        }
    }
}

// ---------------- xd|xs GEMM: [N,75]@[75,750] with f32x2 ----------------
__global__ __launch_bounds__(256) void k_xds(const float* __restrict__ W_pre, int l) {
    __shared__ float As[128][27];
    __shared__ float Bs[25][80];
    int c = blockIdx.x;           // 0..9: part=c/5 (0=dst,1=src), tower=c%5
    int n0 = blockIdx.y * 128;
    int part = c / 5, tw = c - part * 5;
    int tid = threadIdx.x;
    int ty = tid >> 4, tx = tid & 15;
    unsigned long long acc[4][5];
#pragma unroll
    for (int p = 0; p < 4; p++)
#pragma unroll
        for (int j = 0; j < 5; j++) acc[p][j] = 0ULL;
    const float* Wbase = W_pre + (size_t)((l * TOWERS + tw) * 225 + part * F) * F;
    for (int kc = 0; kc < F; kc += 25) {
        for (int idx = tid; idx < 128 * 25; idx += 256) {
            int r = idx / 25, kk = idx - r * 25;
            int n = n0 + r;
            As[r][kk] = (n < N_NODES) ? g_x[n * F + kc + kk] : 0.f;
        }
        for (int idx = tid; idx < 25 * 80; idx += 256) {
            int kk = idx / 80, j = idx - kk * 80;
            Bs[kk][j] = (j < F) ? Wbase[(kc + kk) * F + j] : 0.f;
        }
        __syncthreads();
#pragma unroll 5
        for (int kk = 0; kk < 25; kk++) {
            unsigned long long b2[5];
#pragma unroll
            for (int j = 0; j < 5; j++) {
                float b = Bs[kk][tx * 5 + j];
                b2[j] = f2pk(b, b);
            }
#pragma unroll
            for (int p = 0; p < 4; p++) {
                unsigned long long a2 = f2pk(As[ty + 32 * p][kk], As[ty + 32 * p + 16][kk]);
#pragma unroll
                for (int j = 0; j < 5; j++) acc[p][j] = ffma2(a2, b2[j], acc[p][j]);
            }
        }
        __syncthreads();
    }
    int off = part ? 384 : 0;
#pragma unroll
    for (int p = 0; p < 4; p++) {
        int nlo = n0 + ty + 32 * p, nhi = nlo + 16;
#pragma unroll
        for (int j = 0; j < 5; j++) {
            int jc = tx * 5 + j;
            if (jc < F) {
                float lo, hi;
                f2up(acc[p][j], lo, hi);
                int col = off + tw * F + jc;
                if (nlo < N_NODES) g_xds[(size_t)nlo * XSTRIDE + col] = lo;
                if (nhi < N_NODES) g_xds[(size_t)nhi * XSTRIDE + col] = hi;
            }
        }
    }
}

// ---------------- aggregation: one warp per dst node ----------------
__global__ void k_aggr() {
    int warp = (blockIdx.x * blockDim.x + threadIdx.x) >> 5;
    int lane = threadIdx.x & 31;
    if (warp >= N_NODES) return;
    int n = warp;
    unsigned long long xd2[6], sum2[6], sq2[6];
    float mn[12], mx[12];
    const float4* xdrow = (const float4*)(g_xds + (size_t)n * XSTRIDE);
#pragma unroll
    for (int q = 0; q < 3; q++) {
        float4 v = xdrow[lane * 3 + q];
        xd2[q * 2] = f2pk(v.x, v.y);
        xd2[q * 2 + 1] = f2pk(v.z, v.w);
    }
#pragma unroll
    for (int q = 0; q < 6; q++) { sum2[q] = 0ULL; sq2[q] = 0ULL; }
#pragma unroll
    for (int j = 0; j < 12; j++) { mn[j] = INFINITY; mx[j] = -INFINITY; }
    int e0 = g_rowptr[n], e1 = g_rowptr[n + 1];
    for (int e = e0; e < e1; e++) {
        int s = g_colsrc[e], a = g_colattr[e];
        const float4* xs4 = (const float4*)(g_xds + (size_t)s * XSTRIDE + 384);
        const float4* et4 = (const float4*)(g_et + a * 384);
#pragma unroll
        for (int q = 0; q < 3; q++) {
            float4 xv = xs4[lane * 3 + q];
            float4 ev = et4[lane * 3 + q];
            unsigned long long v0 = fadd2(xd2[2 * q], fadd2(f2pk(xv.x, xv.y), f2pk(ev.x, ev.y)));
            unsigned long long v1 = fadd2(xd2[2 * q + 1], fadd2(f2pk(xv.z, xv.w), f2pk(ev.z, ev.w)));
            sum2[2 * q] = fadd2(sum2[2 * q], v0);
            sum2[2 * q + 1] = fadd2(sum2[2 * q + 1], v1);
            sq2[2 * q] = ffma2(v0, v0, sq2[2 * q]);
            sq2[2 * q + 1] = ffma2(v1, v1, sq2[2 * q + 1]);
            float a0, a1, a2, a3;
            f2up(v0, a0, a1);
            f2up(v1, a2, a3);
            int j = q * 4;
            mn[j] = fminf(mn[j], a0); mx[j] = fmaxf(mx[j], a0);
            mn[j + 1] = fminf(mn[j + 1], a1); mx[j + 1] = fmaxf(mx[j + 1], a1);
            mn[j + 2] = fminf(mn[j + 2], a2); mx[j + 2] = fmaxf(mx[j + 2], a2);
            mn[j + 3] = fminf(mn[j + 3], a3); mx[j + 3] = fmaxf(mx[j + 3], a3);
        }
    }
    float inv = g_invdeg[n];
    bool has = e1 > e0;
#pragma unroll
    for (int q = 0; q < 6; q++) {
        float slo, shi, qlo, qhi;
        f2up(sum2[q], slo, shi);
        f2up(sq2[q], qlo, qhi);
#pragma unroll
        for (int h = 0; h < 2; h++) {
            int f = lane * 12 + q * 2 + h;
            if (f < TF) {
                float sm = h ? shi : slo, sqv = h ? qhi : qlo;
                float mean = sm * inv;
                float var = sqv * inv - mean * mean;
                float sd = sqrtf(fmaxf(var, 0.f) + 1e-5f);
                int j = q * 2 + h;
                float mnv = has ? mn[j] : 0.f;
                float mxv = has ? mx[j] : 0.f;
                int tw = f / F, jj = f - tw * F;
                float* outp = g_aggr + (size_t)n * 1500 + tw * 300 + jj;
                outp[0] = mean;
                outp[75] = mnv;
                outp[150] = mxv;
                outp[225] = sd;
            }
        }
    }
}

// ---------------- S GEMM + scaler combine: per tower [N,300]@[300,45] -> Scomb[N,15/tower]
__global__ __launch_bounds__(256) void k_gemmS(const float* __restrict__ W_post, int l) {
    __shared__ float As[256][27];
    __shared__ float Bs[25][48];
    int t = blockIdx.y;
    int n0 = blockIdx.x * 256;
    int tid = threadIdx.x;
    int ty = tid >> 4, tx = tid & 15;
    unsigned long long acc[8][3];
#pragma unroll
    for (int p = 0; p < 8; p++)
#pragma unroll
        for (int g = 0; g < 3; g++) acc[p][g] = 0ULL;
    for (int kc = 0; kc < 300; kc += 25) {
        for (int idx = tid; idx < 256 * 25; idx += 256) {
            int r = idx / 25, kk = idx - r * 25;
            int n = n0 + r;
            As[r][kk] = (n < N_NODES) ? g_aggr[(size_t)n * 1500 + t * 300 + kc + kk] : 0.f;
        }
        for (int idx = tid; idx < 25 * 48; idx += 256) {
            int kk = idx / 48, j = idx - kk * 48;
            float v = 0.f;
            if (j < 45) {
                int g = j / FOUT, f = j - g * FOUT;
                v = W_post[((size_t)((l * TOWERS + t) * 975 + 75 + g * 300 + kc + kk)) * FOUT + f];
            }
            Bs[kk][j] = v;
        }
        __syncthreads();
#pragma unroll 5
        for (int kk = 0; kk < 25; kk++) {
            unsigned long long b2[3];
#pragma unroll
            for (int g = 0; g < 3; g++) {
                float b = Bs[kk][g * FOUT + tx];
                b2[g] = f2pk(b, b);
            }
#pragma unroll
            for (int p = 0; p < 8; p++) {
                unsigned long long a2 = f2pk(As[ty + 32 * p][kk], As[ty + 32 * p + 16][kk]);
#pragma unroll
                for (int g = 0; g < 3; g++) acc[p][g] = ffma2(a2, b2[g], acc[p][g]);
            }
        }
        __syncthreads();
    }
    if (tx < FOUT) {
#pragma unroll
        for (int p = 0; p < 8; p++) {
            int nlo = n0 + ty + 32 * p, nhi = nlo + 16;
            float g0l, g0h, g1l, g1h, g2l, g2h;
            f2up(acc[p][0], g0l, g0h);
            f2up(acc[p][1], g1l, g1h);
            f2up(acc[p][2], g2l, g2h);
            if (nlo < N_NODES)
                g_S[nlo * F + t * FOUT + tx] = g0l + g_amp[nlo] * g1l + g_att[nlo] * g2l;
            if (nhi < N_NODES)
                g_S[nhi * F + t * FOUT + tx] = g0h + g_amp[nhi] * g1h + g_att[nhi] * g2h;
        }
    }
}

// ---------------- post+lin GEMM (K=150) + BN reduce epilogue ----------------
__global__ __launch_bounds__(256) void k_gemm2(const float* __restrict__ W_lin, int l) {
    __shared__ float As[128][27];
    __shared__ float Bs[25][80];
    __shared__ float red[16][80];
    int n0 = blockIdx.x * 128;
    int tid = threadIdx.x;
    int ty = tid >> 4, tx = tid & 15;
    unsigned long long acc[4][5];
#pragma unroll
    for (int p = 0; p < 4; p++)
#pragma unroll
        for (int j = 0; j < 5; j++) acc[p][j] = 0ULL;
    for (int kc = 0; kc < 150; kc += 25) {
        for (int idx = tid; idx < 128 * 25; idx += 256) {
            int r = idx / 25, kk = idx - r * 25;
            int n = n0 + r;
            int k = kc + kk;
            float v = 0.f;
            if (n < N_NODES)
                v = (k < F) ? g_x[n * F + k] : g_S[n * F + (k - F)];
            As[r][kk] = v;
        }
        for (int idx = tid; idx < 25 * 80; idx += 256) {
            int kk = idx / 80, j = idx - kk * 80;
            int k = kc + kk;
            float v = 0.f;
            if (j < F)
                v = (k < F) ? g_Mfold[k * F + j] : W_lin[(l * F + (k - F)) * F + j];
            Bs[kk][j] = v;
        }
        __syncthreads();
#pragma unroll 5
        for (int kk = 0; kk < 25; kk++) {
            unsigned long long b2[5];
#pragma unroll
            for (int j = 0; j < 5; j++) {
                float b = Bs[kk][tx * 5 + j];
                b2[j] = f2pk(b, b);
            }
#pragma unroll
            for (int p = 0; p < 4; p++) {
                unsigned long long a2 = f2pk(As[ty + 32 * p][kk], As[ty + 32 * p + 16][kk]);
#pragma unroll
                for (int j = 0; j < 5; j++) acc[p][j] = ffma2(a2, b2[j], acc[p][j]);
            }
        }
        __syncthreads();
    }
    // epilogue: y = acc + bfold; bn partials
    float bf[5], s[5], q[5];
#pragma unroll
    for (int j = 0; j < 5; j++) {
        int jc = tx * 5 + j;
        bf[j] = (jc < F) ? g_bfold[jc] : 0.f;
        s[j] = 0.f;
        q[j] = 0.f;
    }
#pragma unroll
    for (int p = 0; p < 4; p++) {
        int nlo = n0 + ty + 32 * p, nhi = nlo + 16;
#pragma unroll
        for (int j = 0; j < 5; j++) {
            int jc = tx * 5 + j;
            if (jc < F) {
                float lo, hi;
                f2up(acc[p][j], lo, hi);
                lo += bf[j];
                hi += bf[j];
                if (nlo < N_NODES) { g_y[nlo * F + jc] = lo; s[j] += lo; q[j] += lo * lo; }
                if (nhi < N_NODES) { g_y[nhi * F + jc] = hi; s[j] += hi; q[j] += hi * hi; }
            }
        }
    }
#pragma unroll
    for (int j = 0; j < 5; j++) red[ty][tx * 5 + j] = s[j];
    __syncthreads();
    if (tid < F) {
        float tot = 0.f;
        for (int yy = 0; yy < 16; yy++) tot += red[yy][tid];
        atomicAdd(&g_bnsum[tid], tot);
    }
    __syncthreads();
#pragma unroll
    for (int j = 0; j < 5; j++) red[ty][tx * 5 + j] = q[j];
    __syncthreads();
    if (tid < F) {
        float tot = 0.f;
        for (int yy = 0; yy < 16; yy++) tot += red[yy][tid];
        atomicAdd(&g_bnsq[tid], tot);
    }
}

// ---------------- BN finalize + apply + ReLU (+ pool on last layer) ------
__global__ void k_bnapply(const float* __restrict__ gamma, const float* __restrict__ beta,
                          const int* __restrict__ batch, int l, int do_pool) {
    __shared__ float sc[F], sh[F];
    int tid = threadIdx.x;
    if (tid < F) {
        float mu = g_bnsum[tid] * (1.f / (float)N_NODES);
        float var = g_bnsq[tid] * (1.f / (float)N_NODES) - mu * mu;
        float r = rsqrtf(var + 1e-5f);
        float s = r * gamma[l * F + tid];
        sc[tid] = s;
        sh[tid] = beta[l * F + tid] - mu * s;
    }
    __syncthreads();
    int base = blockIdx.x * 2048;
#pragma unroll
    for (int o = 0; o < 2048; o += 256) {
        int i = base + o + tid;
        if (i < N_NODES * F) {
            int n = i / F, c = i - n * F;
            float v = fmaxf(g_y[i] * sc[c] + sh[c], 0.f);
            g_x[i] = v;
            if (do_pool) atomicAdd(&g_pooled[batch[n] * F + c], v);
        }
    }
}

// ---------------- final MLP ----------------
__global__ void k_mlp(const float* __restrict__ W1, const float* __restrict__ b1,
                      const float* __restrict__ W2, const float* __restrict__ b2,
                      const float* __restrict__ W3, const float* __restrict__ b3,
                      float* __restrict__ out) {
    __shared__ float w1[75 * 50], w2[50 * 25], w3[25];
    int t = threadIdx.x;
    for (int i = t; i < 75 * 50; i += 256) w1[i] = W1[i];
    for (int i = t; i < 50 * 25; i += 256) w2[i] = W2[i];
    if (t < 25) w3[t] = W3[t];
    __syncthreads();
    if (t >= N_GRAPHS) return;
    const float* p = g_pooled + t * F;
    float h1[50];
    for (int j = 0; j < 50; j++) {
        float a = b1[j];
        for (int c = 0; c < F; c++) a += p[c] * w1[c * 50 + j];
        h1[j] = fmaxf(a, 0.f);
    }
    float h2[25];
    for (int j = 0; j < 25; j++) {
        float a = b2[j];
        for (int c = 0; c < 50; c++) a += h1[c] * w2[c * 25 + j];
        h2[j] = fmaxf(a, 0.f);
    }
    float o = b3[0];
    for (int c = 0; c < 25; c++) o += h2[c] * w3[c];
    out[t] = o;
}

// ---------------- launch ----------------
extern "C" void kernel_launch(void* const* d_in, const int* in_sizes, int n_in,
                              void* d_out, int out_size) {
    const int* x_idx = (const int*)d_in[0];
    const int* edge_index = (const int*)d_in[1];
    const int* eattr = (const int*)d_in[2];
    const int* batch = (const int*)d_in[3];
    const float* node_emb = (const float*)d_in[4];
    const float* edge_emb = (const float*)d_in[5];
    const float* W_edge = (const float*)d_in[6];
    const float* b_edge = (const float*)d_in[7];
    const float* W_pre = (const float*)d_in[8];
    const float* b_pre = (const float*)d_in[9];
    const float* W_post = (const float*)d_in[10];
    const float* b_post = (const float*)d_in[11];
    const float* W_lin = (const float*)d_in[12];
    const float* b_lin = (const float*)d_in[13];
    const float* gamma = (const float*)d_in[14];
    const float* beta = (const float*)d_in[15];
    const float* W1 = (const float*)d_in[16];
    const float* b1 = (const float*)d_in[17];
    const float* W2 = (const float*)d_in[18];
    const float* b2 = (const float*)d_in[19];
    const float* W3 = (const float*)d_in[20];
    const float* b3 = (const float*)d_in[21];
    float* out = (float*)d_out;

    k_init<<<SCAN_BLKS, 256>>>();
    k_gather_count<<<GATHER_BLKS + COUNT_BLKS, 256>>>(x_idx, node_emb, edge_index);
    k_scanA<<<SCAN_BLKS, 256>>>();
    k_scanB<<<1, 128>>>();
    k_scanC<<<SCAN_BLKS, 256>>>();
    k_scatter<<<COUNT_BLKS, 256>>>(edge_index, eattr);

    for (int l = 0; l < 2; l++) {
        k_et_fold<<<N_ATTR + 1, 384>>>(edge_emb, W_edge, b_edge, W_pre, b_pre,
                                       W_post, b_post, W_lin, b_lin, l);
        {
            dim3 grid(10, (N_NODES + 127) / 128);
            k_xds<<<grid, 256>>>(W_pre, l);
        }
        k_aggr<<<(N_NODES * 32 + 255) / 256, 256>>>();
        {
            dim3 grid((N_NODES + 255) / 256, TOWERS);
            k_gemmS<<<grid, 256>>>(W_post, l);
        }
        k_gemm2<<<(N_NODES + 127) / 128, 256>>>(W_lin, l);
        k_bnapply<<<(N_NODES * F + 2047) / 2048, 256>>>(gamma, beta, batch, l, l == 1);
    }

    k_mlp<<<1, 256>>>(W1, b1, W2, b2, W3, b3, out);
}

// round 3
// speedup vs baseline: 1.1628x; 1.0729x over previous
#include <cuda_runtime.h>
#include <cuda_bf16.h>
#include <math.h>

#define N_NODES 20000
#define N_EDGES 320000
#define N_GRAPHS 200
#define TOWERS 5
#define F 75
#define TF 375
#define EDGE_DIM 50
#define N_ATTR 100
#define FOUT 15
#define ROW 384

// ---------------- static scratch (zero-initialized; pads never written) ----
__device__ float g_x[N_NODES * F];
__device__ float g_y[N_NODES * F];
__device__ float g_xd[(size_t)N_NODES * ROW];   // dst-weight projections, cols [0,375) + zero pad
__device__ float g_xs[(size_t)N_NODES * ROW];   // src-weight projections
__device__ float g_aggr[(size_t)N_NODES * 1500];
__device__ float g_S[N_NODES * F];
__device__ float g_et[N_ATTR * ROW];
__device__ float g_Mfold[F * F];
__device__ float g_bfold[F];
__device__ int   g_deg[N_NODES];
__device__ int   g_rowptr[N_NODES + 1];
__device__ int   g_cursor[N_NODES];
__device__ int   g_colsrc[N_EDGES];
__device__ int   g_colattr[N_EDGES];
__device__ float g_amp[N_NODES], g_att[N_NODES], g_invdeg[N_NODES];
__device__ float g_logsum;
__device__ int   g_part[128];
__device__ int   g_partscan[128];
__device__ float g_bnsum[F], g_bnsq[F];
__device__ float g_pooled[N_GRAPHS * F];

// ---------------- f32x2 helpers ----------------
typedef unsigned long long u64;
__device__ __forceinline__ u64 f2bcast(float a) {
    u64 r;
    asm("mov.b64 %0, {%1, %1};" : "=l"(r) : "f"(a));
    return r;
}
__device__ __forceinline__ u64 f2pk(float lo, float hi) {
    u64 r;
    asm("mov.b64 %0, {%1, %2};" : "=l"(r) : "f"(lo), "f"(hi));
    return r;
}
__device__ __forceinline__ void f2up(u64 v, float& lo, float& hi) {
    asm("mov.b64 {%0, %1}, %2;" : "=f"(lo), "=f"(hi) : "l"(v));
}
__device__ __forceinline__ u64 ffma2(u64 a, u64 b, u64 c) {
    u64 d;
    asm("fma.rn.f32x2 %0, %1, %2, %3;" : "=l"(d) : "l"(a), "l"(b), "l"(c));
    return d;
}
__device__ __forceinline__ u64 fadd2(u64 a, u64 b) {
    u64 d;
    asm("add.rn.f32x2 %0, %1, %2;" : "=l"(d) : "l"(a), "l"(b));
    return d;
}

// ---------------- preprocessing ----------------
#define GATHER_BLKS ((N_NODES * F + 255) / 256)
#define COUNT_BLKS ((N_EDGES + 255) / 256)
#define SCAN_BLKS ((N_NODES + 255) / 256)

// relies on g_deg / g_logsum being zero (static init or reset by k_scatter of prev call)
__global__ void k_gather_count(const int* __restrict__ x_idx, const float* __restrict__ emb,
                               const int* __restrict__ ei) {
    int b = blockIdx.x;
    if (b < GATHER_BLKS) {
        int i = b * 256 + threadIdx.x;
        if (i < N_NODES * F) {
            int n = i / F, f = i - n * F;
            g_x[i] = emb[x_idx[n] * F + f];
        }
    } else {
        int i = (b - GATHER_BLKS) * 256 + threadIdx.x;
        if (i < N_EDGES) atomicAdd(&g_deg[ei[N_EDGES + i]], 1);
    }
}

__global__ void k_scanA() {
    __shared__ int ss[256];
    __shared__ float ls[256];
    int b = blockIdx.x, tid = threadIdx.x;
    int n = b * 256 + tid;
    int d = (n < N_NODES) ? g_deg[n] : 0;
    ss[tid] = d;
    ls[tid] = (n < N_NODES) ? logf((float)d + 1.f) : 0.f;
    __syncthreads();
    for (int o = 128; o; o >>= 1) {
        if (tid < o) { ss[tid] += ss[tid + o]; ls[tid] += ls[tid + o]; }
        __syncthreads();
    }
    if (tid == 0) { g_part[b] = ss[0]; atomicAdd(&g_logsum, ls[0]); }
}

__global__ void k_scanB() {
    __shared__ int s[128];
    int t = threadIdx.x;
    int own = (t < SCAN_BLKS) ? g_part[t] : 0;
    s[t] = own;
    __syncthreads();
    for (int o = 1; o < 128; o <<= 1) {
        int v = (t >= o) ? s[t - o] : 0;
        __syncthreads();
        s[t] += v;
        __syncthreads();
    }
    if (t < SCAN_BLKS) g_partscan[t] = s[t] - own;
}

__global__ void k_scanC() {
    __shared__ int s[256];
    int b = blockIdx.x, tid = threadIdx.x;
    int n = b * 256 + tid;
    int d = (n < N_NODES) ? g_deg[n] : 0;
    int own = d;
    s[tid] = d;
    __syncthreads();
    for (int o = 1; o < 256; o <<= 1) {
        int v = (tid >= o) ? s[tid - o] : 0;
        __syncthreads();
        s[tid] += v;
        __syncthreads();
    }
    int excl = s[tid] - own + g_partscan[b];
    if (n < N_NODES) {
        g_rowptr[n] = excl;
        g_cursor[n] = excl;
        float avg = g_logsum * (1.f / (float)N_NODES);
        float dc = fmaxf((float)d, 1.f);
        float L = logf(dc + 1.f);
        g_amp[n] = L / avg;
        g_att[n] = avg / L;
        g_invdeg[n] = 1.f / dc;
        if (n == N_NODES - 1) g_rowptr[N_NODES] = excl + d;
    }
    if (n < N_GRAPHS * F) g_pooled[n] = 0.f;   // reset pool accumulator for this call
}

__global__ void k_scatter(const int* __restrict__ ei, const int* __restrict__ ea) {
    int i = blockIdx.x * 256 + threadIdx.x;
    if (i < N_EDGES) {
        int dst = ei[N_EDGES + i];
        int pos = atomicAdd(&g_cursor[dst], 1);
        g_colsrc[pos] = ei[i];
        g_colattr[pos] = ea[i];
    }
    // reset counters for the NEXT invocation (deg/logsum fully consumed above)
    if (i < N_NODES) g_deg[i] = 0;
    if (i == 0) g_logsum = 0.f;
}

// ---------------- per-layer: et table + Mfold + bn zero ----------------
__global__ void k_et_fold(const float* __restrict__ edge_emb, const float* __restrict__ W_edge,
                          const float* __restrict__ b_edge, const float* __restrict__ W_pre,
                          const float* __restrict__ b_pre, const float* __restrict__ W_post,
                          const float* __restrict__ b_post, const float* __restrict__ W_lin,
                          const float* __restrict__ b_lin, int l) {
    int a = blockIdx.x, t = threadIdx.x;
    if (a < N_ATTR) {
        __shared__ float e75[F];
        if (t < F) {
            float acc = b_edge[l * F + t];
            for (int d = 0; d < EDGE_DIM; d++)
                acc += edge_emb[a * EDGE_DIM + d] * W_edge[(l * EDGE_DIM + d) * F + t];
            e75[t] = acc;
        }
        __syncthreads();
        if (t < TF) {
            int tw = t / F, f = t - tw * F;
            float acc = b_pre[(l * TOWERS + tw) * F + f];
            const float* Wp = W_pre + ((size_t)((l * TOWERS + tw) * 225 + 150)) * F + f;
            for (int c = 0; c < F; c++) acc += e75[c] * Wp[c * F];
            g_et[a * ROW + t] = acc;
        }
    } else {
        for (int i = t; i < F * F; i += 384) {
            int c = i / F, o = i - c * F;
            float acc = 0.f;
            for (int tf = 0; tf < F; tf++) {
                int tw = tf / FOUT, f = tf - tw * FOUT;
                acc += W_post[((size_t)((l * TOWERS + tw) * 975 + c)) * FOUT + f] *
                       W_lin[(l * F + tf) * F + o];
            }
            g_Mfold[i] = acc;
        }
        if (t < F) {
            float bf = b_lin[l * F + t];
            for (int tf = 0; tf < F; tf++) {
                int tw = tf / FOUT, f = tf - tw * FOUT;
                bf += b_post[(l * TOWERS + tw) * FOUT + f] * W_lin[(l * F + tf) * F + t];
            }
            g_bfold[t] = bf;
            g_bnsum[t] = 0.f;
            g_bnsq[t] = 0.f;
        }
    }
}

// ---------------- xd|xs GEMM: per (part,tower): [N,75]@[75,75] ----------------
// block: 128 nodes x 80 cols (75 used). 256 thr: ty=tid>>3 (32 row-groups), tx=tid&7.
// thread tile: 4 nodes (r=ty+32i) x 5 col-pairs (p=tx*5+j).
__global__ __launch_bounds__(256) void k_xds(const float* __restrict__ W_pre, int l) {
    __shared__ __align__(16) float As[128][25];
    __shared__ __align__(16) float Bs[25][80];
    int c = blockIdx.x;
    int n0 = blockIdx.y * 128;
    int part = c / 5, tw = c - part * 5;
    int tid = threadIdx.x;
    int ty = tid >> 3, tx = tid & 7;
    u64 acc[4][5];
#pragma unroll
    for (int i = 0; i < 4; i++)
#pragma unroll
        for (int j = 0; j < 5; j++) acc[i][j] = 0ULL;
    const float* Wbase = W_pre + (size_t)((l * TOWERS + tw) * 225 + part * F) * F;
    for (int kc = 0; kc < F; kc += 25) {
        for (int idx = tid; idx < 128 * 25; idx += 256) {
            int r = idx / 25, kk = idx - r * 25;
            int n = n0 + r;
            As[r][kk] = (n < N_NODES) ? g_x[n * F + kc + kk] : 0.f;
        }
        for (int idx = tid; idx < 25 * 80; idx += 256) {
            int kk = idx / 80, j = idx - kk * 80;
            Bs[kk][j] = (j < F) ? Wbase[(kc + kk) * F + j] : 0.f;
        }
        __syncthreads();
#pragma unroll 5
        for (int kk = 0; kk < 25; kk++) {
            u64 b2[5];
#pragma unroll
            for (int j = 0; j < 5; j++)
                b2[j] = *(const u64*)&Bs[kk][2 * (tx * 5 + j)];
#pragma unroll
            for (int i = 0; i < 4; i++) {
                u64 a2 = f2bcast(As[ty + 32 * i][kk]);
#pragma unroll
                for (int j = 0; j < 5; j++) acc[i][j] = ffma2(a2, b2[j], acc[i][j]);
            }
        }
        __syncthreads();
    }
    float* dst = part ? g_xs : g_xd;
#pragma unroll
    for (int i = 0; i < 4; i++) {
        int n = n0 + ty + 32 * i;
        if (n >= N_NODES) continue;
        float* row = dst + (size_t)n * ROW + tw * F;
#pragma unroll
        for (int j = 0; j < 5; j++) {
            int jc = 2 * (tx * 5 + j);
            float lo, hi;
            f2up(acc[i][j], lo, hi);
            if (jc < F) row[jc] = lo;
            if (jc + 1 < F) row[jc + 1] = hi;
        }
    }
}

// ---------------- aggregation: one warp per dst node ----------------
__global__ void k_aggr() {
    int warp = (blockIdx.x * blockDim.x + threadIdx.x) >> 5;
    int lane = threadIdx.x & 31;
    if (warp >= N_NODES) return;
    int n = warp;
    u64 xd2[6], sum2[6], sq2[6];
    float mn[12], mx[12];
    const float4* xdrow = (const float4*)(g_xd + (size_t)n * ROW);
#pragma unroll
    for (int q = 0; q < 3; q++) {
        float4 v = xdrow[lane * 3 + q];
        xd2[q * 2] = f2pk(v.x, v.y);
        xd2[q * 2 + 1] = f2pk(v.z, v.w);
    }
#pragma unroll
    for (int q = 0; q < 6; q++) { sum2[q] = 0ULL; sq2[q] = 0ULL; }
#pragma unroll
    for (int j = 0; j < 12; j++) { mn[j] = INFINITY; mx[j] = -INFINITY; }
    int e0 = g_rowptr[n], e1 = g_rowptr[n + 1];
#pragma unroll 2
    for (int e = e0; e < e1; e++) {
        int s = g_colsrc[e], a = g_colattr[e];
        const float4* xs4 = (const float4*)(g_xs + (size_t)s * ROW);
        const float4* et4 = (const float4*)(g_et + a * ROW);
#pragma unroll
        for (int q = 0; q < 3; q++) {
            float4 xv = xs4[lane * 3 + q];
            float4 ev = et4[lane * 3 + q];
            u64 v0 = fadd2(xd2[2 * q], fadd2(f2pk(xv.x, xv.y), f2pk(ev.x, ev.y)));
            u64 v1 = fadd2(xd2[2 * q + 1], fadd2(f2pk(xv.z, xv.w), f2pk(ev.z, ev.w)));
            sum2[2 * q] = fadd2(sum2[2 * q], v0);
            sum2[2 * q + 1] = fadd2(sum2[2 * q + 1], v1);
            sq2[2 * q] = ffma2(v0, v0, sq2[2 * q]);
            sq2[2 * q + 1] = ffma2(v1, v1, sq2[2 * q + 1]);
            float a0, a1, a2, a3;
            f2up(v0, a0, a1);
            f2up(v1, a2, a3);
            int j = q * 4;
            mn[j] = fminf(mn[j], a0); mx[j] = fmaxf(mx[j], a0);
            mn[j + 1] = fminf(mn[j + 1], a1); mx[j + 1] = fmaxf(mx[j + 1], a1);
            mn[j + 2] = fminf(mn[j + 2], a2); mx[j + 2] = fmaxf(mx[j + 2], a2);
            mn[j + 3] = fminf(mn[j + 3], a3); mx[j + 3] = fmaxf(mx[j + 3], a3);
        }
    }
    float inv = g_invdeg[n];
    bool has = e1 > e0;
#pragma unroll
    for (int q = 0; q < 6; q++) {
        float slo, shi, qlo, qhi;
        f2up(sum2[q], slo, shi);
        f2up(sq2[q], qlo, qhi);
#pragma unroll
        for (int h = 0; h < 2; h++) {
            int f = lane * 12 + q * 2 + h;
            if (f < TF) {
                float sm = h ? shi : slo, sqv = h ? qhi : qlo;
                float mean = sm * inv;
                float var = sqv * inv - mean * mean;
                float sd = sqrtf(fmaxf(var, 0.f) + 1e-5f);
                int j = q * 2 + h;
                float mnv = has ? mn[j] : 0.f;
                float mxv = has ? mx[j] : 0.f;
                int tw = f / F, jj = f - tw * F;
                float* outp = g_aggr + (size_t)n * 1500 + tw * 300 + jj;
                outp[0] = mean;
                outp[75] = mnv;
                outp[150] = mxv;
                outp[225] = sd;
            }
        }
    }
}

// ---------------- S GEMM + scaler combine ----------------
// per tower: [N,300]@[300,48pad]; cols laid out [g0:16][g1:16][g2:16], f<15 valid.
// block: 256 nodes. 256 thr: ty=tid>>3 (32), tx=tid&7.
// thread tile: 8 nodes (r=ty+32i) x pairs {tx, 8+tx, 16+tx} (same f-pos in the 3 groups).
__global__ __launch_bounds__(256) void k_gemmS(const float* __restrict__ W_post, int l) {
    __shared__ __align__(16) float As[256][25];
    __shared__ __align__(16) float Bs[25][48];
    int t = blockIdx.y;
    int n0 = blockIdx.x * 256;
    int tid = threadIdx.x;
    int ty = tid >> 3, tx = tid & 7;
    u64 acc[8][3];
#pragma unroll
    for (int i = 0; i < 8; i++)
#pragma unroll
        for (int g = 0; g < 3; g++) acc[i][g] = 0ULL;
    for (int kc = 0; kc < 300; kc += 25) {
        for (int idx = tid; idx < 256 * 25; idx += 256) {
            int r = idx / 25, kk = idx - r * 25;
            int n = n0 + r;
            As[r][kk] = (n < N_NODES) ? g_aggr[(size_t)n * 1500 + t * 300 + kc + kk] : 0.f;
        }
        for (int idx = tid; idx < 25 * 48; idx += 256) {
            int kk = idx / 48, j = idx - kk * 48;
            int g = j >> 4, f = j & 15;
            Bs[kk][j] = (f < FOUT)
                ? W_post[((size_t)((l * TOWERS + t) * 975 + 75 + g * 300 + kc + kk)) * FOUT + f]
                : 0.f;
        }
        __syncthreads();
#pragma unroll 5
        for (int kk = 0; kk < 25; kk++) {
            u64 b0 = *(const u64*)&Bs[kk][2 * tx];
            u64 b1 = *(const u64*)&Bs[kk][16 + 2 * tx];
            u64 b2 = *(const u64*)&Bs[kk][32 + 2 * tx];
#pragma unroll
            for (int i = 0; i < 8; i++) {
                u64 a2 = f2bcast(As[ty + 32 * i][kk]);
                acc[i][0] = ffma2(a2, b0, acc[i][0]);
                acc[i][1] = ffma2(a2, b1, acc[i][1]);
                acc[i][2] = ffma2(a2, b2, acc[i][2]);
            }
        }
        __syncthreads();
    }
#pragma unroll
    for (int i = 0; i < 8; i++) {
        int n = n0 + ty + 32 * i;
        if (n >= N_NODES) continue;
        float amp = g_amp[n], att = g_att[n];
        float a0l, a0h, a1l, a1h, a2l, a2h;
        f2up(acc[i][0], a0l, a0h);
        f2up(acc[i][1], a1l, a1h);
        f2up(acc[i][2], a2l, a2h);
        float* row = g_S + n * F + t * FOUT;
        row[2 * tx] = a0l + amp * a1l + att * a2l;
        if (2 * tx + 1 < FOUT) row[2 * tx + 1] = a0h + amp * a1h + att * a2h;
    }
}

// ---------------- post+lin GEMM (K=150) + BN reduce ----------------
// block: 128 nodes x 80 cols (75 used). thread tile 4 nodes x 5 pairs. 256 thr.
__global__ __launch_bounds__(256) void k_gemm2(const float* __restrict__ W_lin, int l) {
    __shared__ __align__(16) float As[128][25];
    __shared__ __align__(16) float Bs[25][80];
    __shared__ float red[32][80];
    int n0 = blockIdx.x * 128;
    int tid = threadIdx.x;
    int ty = tid >> 3, tx = tid & 7;
    u64 acc[4][5];
#pragma unroll
    for (int i = 0; i < 4; i++)
#pragma unroll
        for (int j = 0; j < 5; j++) acc[i][j] = 0ULL;
    for (int kc = 0; kc < 150; kc += 25) {
        for (int idx = tid; idx < 128 * 25; idx += 256) {
            int r = idx / 25, kk = idx - r * 25;
            int n = n0 + r;
            int k = kc + kk;
            float v = 0.f;
            if (n < N_NODES) v = (k < F) ? g_x[n * F + k] : g_S[n * F + (k - F)];
            As[r][kk] = v;
        }
        for (int idx = tid; idx < 25 * 80; idx += 256) {
            int kk = idx / 80, j = idx - kk * 80;
            int k = kc + kk;
            float v = 0.f;
            if (j < F) v = (k < F) ? g_Mfold[k * F + j] : W_lin[(l * F + (k - F)) * F + j];
            Bs[kk][j] = v;
        }
        __syncthreads();
#pragma unroll 5
        for (int kk = 0; kk < 25; kk++) {
            u64 b2[5];
#pragma unroll
            for (int j = 0; j < 5; j++)
                b2[j] = *(const u64*)&Bs[kk][2 * (tx * 5 + j)];
#pragma unroll
            for (int i = 0; i < 4; i++) {
                u64 a2 = f2bcast(As[ty + 32 * i][kk]);
#pragma unroll
                for (int j = 0; j < 5; j++) acc[i][j] = ffma2(a2, b2[j], acc[i][j]);
            }
        }
        __syncthreads();
    }
    // epilogue: add bfold, store y, BN partials
    float s[10], q[10];
#pragma unroll
    for (int j = 0; j < 10; j++) { s[j] = 0.f; q[j] = 0.f; }
#pragma unroll
    for (int i = 0; i < 4; i++) {
        int n = n0 + ty + 32 * i;
        if (n >= N_NODES) continue;
#pragma unroll
        for (int j = 0; j < 5; j++) {
            int jc = 2 * (tx * 5 + j);
            float lo, hi;
            f2up(acc[i][j], lo, hi);
            if (jc < F) {
                float v = lo + g_bfold[jc];
                g_y[n * F + jc] = v;
                s[2 * j] += v; q[2 * j] += v * v;
            }
            if (jc + 1 < F) {
                float v = hi + g_bfold[jc + 1];
                g_y[n * F + jc + 1] = v;
                s[2 * j + 1] += v; q[2 * j + 1] += v * v;
            }
        }
    }
#pragma unroll
    for (int j = 0; j < 10; j++) red[ty][tx * 10 + j] = s[j];
    __syncthreads();
    if (tid < F) {
        float tot = 0.f;
        for (int yy = 0; yy < 32; yy++) tot += red[yy][tid];
        atomicAdd(&g_bnsum[tid], tot);
    }
    __syncthreads();
#pragma unroll
    for (int j = 0; j < 10; j++) red[ty][tx * 10 + j] = q[j];
    __syncthreads();
    if (tid < F) {
        float tot = 0.f;
        for (int yy = 0; yy < 32; yy++) tot += red[yy][tid];
        atomicAdd(&g_bnsq[tid], tot);
    }
}

// ---------------- BN finalize + apply + ReLU (+ pool on last layer) ------
__global__ void k_bnapply(const float* __restrict__ gamma, const float* __restrict__ beta,
                          const int* __restrict__ batch, int l, int do_pool) {
    __shared__ float sc[F], sh[F];
    int tid = threadIdx.x;
    if (tid < F) {
        float mu = g_bnsum[tid] * (1.f / (float)N_NODES);
        float var = g_bnsq[tid] * (1.f / (float)N_NODES) - mu * mu;
        float r = rsqrtf(var + 1e-5f);
        float s = r * gamma[l * F + tid];
        sc[tid] = s;
        sh[tid] = beta[l * F + tid] - mu * s;
    }
    __syncthreads();
    int base = blockIdx.x * 2048;
#pragma unroll
    for (int o = 0; o < 2048; o += 256) {
        int i = base + o + tid;
        if (i < N_NODES * F) {
            int n = i / F, c = i - n * F;
            float v = fmaxf(g_y[i] * sc[c] + sh[c], 0.f);
            g_x[i] = v;
            if (do_pool) atomicAdd(&g_pooled[batch[n] * F + c], v);
        }
    }
}

// ---------------- final MLP ----------------
__global__ void k_mlp(const float* __restrict__ W1, const float* __restrict__ b1,
                      const float* __restrict__ W2, const float* __restrict__ b2,
                      const float* __restrict__ W3, const float* __restrict__ b3,
                      float* __restrict__ out) {
    __shared__ float w1[75 * 50], w2[50 * 25], w3[25];
    int t = threadIdx.x;
    for (int i = t; i < 75 * 50; i += 256) w1[i] = W1[i];
    for (int i = t; i < 50 * 25; i += 256) w2[i] = W2[i];
    if (t < 25) w3[t] = W3[t];
    __syncthreads();
    if (t >= N_GRAPHS) return;
    const float* p = g_pooled + t * F;
    float h1[50];
    for (int j = 0; j < 50; j++) {
        float a = b1[j];
        for (int c = 0; c < F; c++) a += p[c] * w1[c * 50 + j];
        h1[j] = fmaxf(a, 0.f);
    }
    float h2[25];
    for (int j = 0; j < 25; j++) {
        float a = b2[j];
        for (int c = 0; c < 50; c++) a += h1[c] * w2[c * 25 + j];
        h2[j] = fmaxf(a, 0.f);
    }
    float o = b3[0];
    for (int c = 0; c < 25; c++) o += h2[c] * w3[c];
    out[t] = o;
}

// ---------------- launch ----------------
extern "C" void kernel_launch(void* const* d_in, const int* in_sizes, int n_in,
                              void* d_out, int out_size) {
    const int* x_idx = (const int*)d_in[0];
    const int* edge_index = (const int*)d_in[1];
    const int* eattr = (const int*)d_in[2];
    const int* batch = (const int*)d_in[3];
    const float* node_emb = (const float*)d_in[4];
    const float* edge_emb = (const float*)d_in[5];
    const float* W_edge = (const float*)d_in[6];
    const float* b_edge = (const float*)d_in[7];
    const float* W_pre = (const float*)d_in[8];
    const float* b_pre = (const float*)d_in[9];
    const float* W_post = (const float*)d_in[10];
    const float* b_post = (const float*)d_in[11];
    const float* W_lin = (const float*)d_in[12];
    const float* b_lin = (const float*)d_in[13];
    const float* gamma = (const float*)d_in[14];
    const float* beta = (const float*)d_in[15];
    const float* W1 = (const float*)d_in[16];
    const float* b1 = (const float*)d_in[17];
    const float* W2 = (const float*)d_in[18];
    const float* b2 = (const float*)d_in[19];
    const float* W3 = (const float*)d_in[20];
    const float* b3 = (const float*)d_in[21];
    float* out = (float*)d_out;

    k_gather_count<<<GATHER_BLKS + COUNT_BLKS, 256>>>(x_idx, node_emb, edge_index); // 1
    k_scanA<<<SCAN_BLKS, 256>>>();                                                  // 2
    k_scanB<<<1, 128>>>();                                                          // 3
    k_scanC<<<SCAN_BLKS, 256>>>();                                                  // 4
    k_scatter<<<COUNT_BLKS, 256>>>(edge_index, eattr);                              // 5

    for (int l = 0; l < 2; l++) {
        {
            dim3 grid(10, (N_NODES + 127) / 128);
            k_xds<<<grid, 256>>>(W_pre, l);                                         // 6 on l=0
        }
        k_et_fold<<<N_ATTR + 1, 384>>>(edge_emb, W_edge, b_edge, W_pre, b_pre,
                                       W_post, b_post, W_lin, b_lin, l);
        k_aggr<<<(N_NODES * 32 + 255) / 256, 256>>>();
        {
            dim3 grid((N_NODES + 255) / 256, TOWERS);
            k_gemmS<<<grid, 256>>>(W_post, l);
        }
        k_gemm2<<<(N_NODES + 127) / 128, 256>>>(W_lin, l);
        k_bnapply<<<(N_NODES * F + 2047) / 2048, 256>>>(gamma, beta, batch, l, l == 1);
    }

    k_mlp<<<1, 256>>>(W1, b1, W2, b2, W3, b3, out);
}